// round 11
// baseline (speedup 1.0000x reference)
#include <cuda_runtime.h>

#define E 8
#define DDIM 1024
#define NW 8                      // warps per block
#define TPB (NW * 32)             // 256
#define GRID 128                  // 128 * 256 = 32768 tokens exactly
#define CFLOAT 64                 // floats per token per chunk
#define CSLOT (CFLOAT / 4)        // 16 float4 slots
#define NCH (DDIM / CFLOAT)       // 16 chunks
#define STG 3                     // warp-private pipeline stages
#define WBUF (32 * CFLOAT)        // floats per stage per warp (2048)
#define SMEM_FLOATS (E * DDIM + NW * STG * WBUF)
#define SMEM_BYTES (SMEM_FLOATS * 4)   // 32KB W + 192KB x rings = 224KB

// Global accumulators. Zero-initialized at module load; the LAST block resets
// them after consuming, so every launch / graph replay sees zeros on entry.
__device__ float g_prob_sum[E];
__device__ float g_ent_sum;
__device__ unsigned g_cnt[E];
__device__ unsigned g_done;

// Warp-private chunk stage: each lane copies part of the 32 rows THIS warp's
// lanes will read. Completion: per-thread wait_group + __syncwarp (no BAR).
__device__ __forceinline__ void warp_issue(const float* __restrict__ x, float* wbuf,
                                           int tok0, int c, int lane, int N) {
    float* buf = wbuf + (c % STG) * WBUF;
#pragma unroll
    for (int k = 0; k < 16; ++k) {
        int i = lane + k * 32;
        int r = i >> 4;                         // row 0..31
        int s = i & 15;                         // float4 slot 0..15
        int gt = tok0 + r; if (gt > N - 1) gt = N - 1;
        const float* src = x + (size_t)gt * DDIM + c * CFLOAT + s * 4;
        float* dst = buf + r * CFLOAT + ((s ^ (r & 15)) << 2);
        unsigned d = (unsigned)__cvta_generic_to_shared(dst);
        asm volatile("cp.async.cg.shared.global [%0], [%1], 16;\n" :: "r"(d), "l"(src));
    }
    asm volatile("cp.async.commit_group;\n");
}

__global__ __launch_bounds__(TPB, 1)
void router_main(const float* __restrict__ x, const float* __restrict__ Wg,
                 const int* __restrict__ pk, float* __restrict__ out,
                 int N, int tok_per_blk) {
    extern __shared__ float smem[];
    float* sW = smem;                              // [E*DDIM]
    float* sx = smem + E * DDIM;                   // [NW][STG][32][CFLOAT]
    __shared__ float sh_psum[E];
    __shared__ unsigned sh_cnt[E];
    __shared__ float sh_ent;

    int tid = threadIdx.x;
    int wid = tid >> 5;
    int lane = tid & 31;
    int tok0 = blockIdx.x * tok_per_blk + wid * 32;
    float* wbuf = sx + wid * (STG * WBUF);

    // Start HBM traffic immediately (warp-private buffers: no barrier needed)
    warp_issue(x, wbuf, tok0, 0, lane, N);
    warp_issue(x, wbuf, tok0, 1, lane, N);

    // Stage W (32KB) into shared; single block barrier for the whole kernel
    for (int i = tid; i < (E * DDIM) / 4; i += TPB)
        ((float4*)sW)[i] = ((const float4*)Wg)[i];
    if (tid < E) { sh_psum[tid] = 0.f; sh_cnt[tid] = 0u; }
    if (tid == 0) sh_ent = 0.f;
    __syncthreads();

    int token = tok0 + lane;
    bool valid = (wid * 32 + lane < tok_per_blk) && (token < N);

    const float4* __restrict__ w4 = (const float4*)sW;
    int swz = lane & 15;

    // STRICT ascending-d scalar fmaf chain per (token, expert) — bit-identical
    // to the passing kernels (one flipped top-k index fails the test).
    float acc[E];
#pragma unroll
    for (int e = 0; e < E; ++e) acc[e] = 0.f;

    for (int c = 0; c < NCH; ++c) {
        if (c < NCH - 1) asm volatile("cp.async.wait_group 1;\n" ::: "memory");
        else             asm volatile("cp.async.wait_group 0;\n" ::: "memory");
        __syncwarp();

        const float4* xrow = (const float4*)(wbuf + (c % STG) * WBUF + lane * CFLOAT);
#pragma unroll
        for (int j = 0; j < CSLOT; ++j) {
            float4 xv = xrow[j ^ swz];
#pragma unroll
            for (int e = 0; e < E; ++e) {
                float4 wv = w4[e * (DDIM / 4) + c * CSLOT + j]; // warp-uniform broadcast
                acc[e] = fmaf(xv.x, wv.x, acc[e]);
                acc[e] = fmaf(xv.y, wv.y, acc[e]);
                acc[e] = fmaf(xv.z, wv.z, acc[e]);
                acc[e] = fmaf(xv.w, wv.w, acc[e]);
            }
        }
        if (c + 2 < NCH) warp_issue(x, wbuf, tok0, c + 2, lane, N);
    }

    // ---- epilogue: softmax / top-k / stats, all in registers ----
    int kk = *pk; kk = kk < 1 ? 1 : (kk > E ? E : kk);
    float* out_dw  = out;
    float* out_idx = out + (size_t)N * kk;
    float* out_lg  = out + (size_t)2 * N * kk;

    if (valid) {
        float4* lp = (float4*)(out_lg + (size_t)token * E);
        lp[0] = make_float4(acc[0], acc[1], acc[2], acc[3]);
        lp[1] = make_float4(acc[4], acc[5], acc[6], acc[7]);
    }

    float m = acc[0];
#pragma unroll
    for (int e = 1; e < E; ++e) m = fmaxf(m, acc[e]);
    float p[E], s = 0.f;
#pragma unroll
    for (int e = 0; e < E; ++e) { p[e] = __expf(acc[e] - m); s += p[e]; }
    float inv = 1.f / s;
    float logs = __logf(s);
    float ent = 0.f;
#pragma unroll
    for (int e = 0; e < E; ++e) ent -= (p[e] * inv) * (acc[e] - m - logs);

    // top-k (values descending, ties -> lower index, matching lax.top_k)
    unsigned selmask = 0;
    float tmp[E];
#pragma unroll
    for (int e = 0; e < E; ++e) tmp[e] = p[e];
#pragma unroll
    for (int r = 0; r < E; ++r) {
        if (r < kk) {
            int bi = 0; float bv = tmp[0];
#pragma unroll
            for (int e = 1; e < E; ++e) { if (tmp[e] > bv) { bv = tmp[e]; bi = e; } }
            if (valid) {
                out_dw [(size_t)token * kk + r] = bv * inv;
                out_idx[(size_t)token * kk + r] = (float)bi;
            }
            selmask |= (1u << bi);
#pragma unroll
            for (int e = 0; e < E; ++e) if (e == bi) tmp[e] = -1.f;
        }
    }

    if (!valid) { ent = 0.f; selmask = 0u; inv = 0.f; }

    // Warp reduction -> shared atomics -> one global atomic set per block
    float entw = ent;
#pragma unroll
    for (int o = 16; o > 0; o >>= 1) entw += __shfl_xor_sync(0xffffffffu, entw, o);
    float psum[E];
#pragma unroll
    for (int e = 0; e < E; ++e) {
        float v = p[e] * inv;
#pragma unroll
        for (int o = 16; o > 0; o >>= 1) v += __shfl_xor_sync(0xffffffffu, v, o);
        psum[e] = v;
    }
    bool lane0 = (lane == 0);
    if (lane0) atomicAdd(&sh_ent, entw);
#pragma unroll
    for (int e = 0; e < E; ++e) {
        unsigned b = __ballot_sync(0xffffffffu, (selmask >> e) & 1u);
        if (lane0) {
            atomicAdd(&sh_cnt[e], (unsigned)__popc(b));
            atomicAdd(&sh_psum[e], psum[e]);
        }
    }
    __syncthreads();
    if (tid < E) {
        atomicAdd(&g_cnt[tid], sh_cnt[tid]);
        atomicAdd(&g_prob_sum[tid], sh_psum[tid]);
    }
    if (tid == E) atomicAdd(&g_ent_sum, sh_ent);

    // ---- last-block-done finalize (fused; single launch) ----
    __threadfence();
    __shared__ unsigned sh_last;
    if (tid == 0) sh_last = atomicAdd(&g_done, 1u);
    __syncthreads();
    if (sh_last != gridDim.x - 1u) return;

    if (tid == 0) {
        float* base = out + (size_t)2 * N * kk + (size_t)N * E;
        long long total_cap = (long long)((double)N * (double)kk * 1.25);
        long long per_cap = total_cap / E; if (per_cap < 1) per_cap = 1;
        float invN = 1.f / (float)N;
        float lb = 0.f; int nd = 0;
        for (int e = 0; e < E; ++e) {
            float cnt = (float)g_cnt[e];
            float usage = cnt * invN;
            float avg = g_prob_sum[e] * invN;
            lb += usage * avg;
            if ((long long)g_cnt[e] > per_cap) nd++;
            base[3 + e] = usage;
        }
        base[0] = lb * (float)E;
        float entm = g_ent_sum * invN;
        float rel = logf((float)E) - entm;
        base[1] = rel > 0.f ? rel : 0.f;
        base[2] = (float)nd;

        // Reset accumulators for the next launch / graph replay.
        for (int e = 0; e < E; ++e) { g_cnt[e] = 0u; g_prob_sum[e] = 0.f; }
        g_ent_sum = 0.f;
        g_done = 0u;
    }
}

extern "C" void kernel_launch(void* const* d_in, const int* in_sizes, int n_in,
                              void* d_out, int out_size) {
    const float* x = (const float*)d_in[0];
    const float* W = (const float*)d_in[1];
    const int*  pk = (const int*)d_in[2];
    int N = in_sizes[0] / DDIM;
    float* out = (float*)d_out;

    int grid = GRID;
    int tok_per_blk = (N + grid - 1) / grid;       // 256 for N=32768 (exact)
    if (tok_per_blk > TPB) {                        // safety for other shapes
        grid = (N + TPB - 1) / TPB;
        tok_per_blk = TPB;
    }
    cudaFuncSetAttribute(router_main, cudaFuncAttributeMaxDynamicSharedMemorySize, SMEM_BYTES);
    router_main<<<grid, TPB, SMEM_BYTES>>>(x, W, pk, out, N, tok_per_blk);
}

// round 12
// speedup vs baseline: 1.0907x; 1.0907x over previous
#include <cuda_runtime.h>

#define E 8
#define DDIM 1024
#define NW 7                      // warps per block
#define TPB (NW * 32)             // 224
#define GRID 148
#define CFLOAT 64                 // floats per token per chunk
#define CSLOT (CFLOAT / 4)        // 16 float4 slots
#define NCH (DDIM / CFLOAT)       // 16 chunks
#define STG 3                     // warp-private pipeline stages
#define WBUF (32 * CFLOAT)        // floats per stage per warp (2048)
#define SMEM_FLOATS (E * DDIM + NW * STG * WBUF)
#define SMEM_BYTES (SMEM_FLOATS * 4)   // 32KB W + 168KB x rings = 200KB

// Global accumulators. Zero-initialized at module load; the LAST block resets
// them after consuming, so every launch / graph replay sees zeros on entry.
__device__ float g_prob_sum[E];
__device__ float g_ent_sum;
__device__ unsigned g_cnt[E];
__device__ unsigned g_done;

// Warp-private chunk stage: each lane copies part of the 32 rows THIS warp's
// lanes will read. Completion: per-thread wait_group + __syncwarp (no BAR).
__device__ __forceinline__ void warp_issue(const float* __restrict__ x, float* wbuf,
                                           int tok0, int c, int lane, int N) {
    float* buf = wbuf + (c % STG) * WBUF;
#pragma unroll
    for (int k = 0; k < 16; ++k) {
        int i = lane + k * 32;
        int r = i >> 4;                         // row 0..31
        int s = i & 15;                         // float4 slot 0..15
        int gt = tok0 + r; if (gt > N - 1) gt = N - 1;
        const float* src = x + (size_t)gt * DDIM + c * CFLOAT + s * 4;
        float* dst = buf + r * CFLOAT + ((s ^ (r & 15)) << 2);
        unsigned d = (unsigned)__cvta_generic_to_shared(dst);
        asm volatile("cp.async.cg.shared.global [%0], [%1], 16;\n" :: "r"(d), "l"(src));
    }
    asm volatile("cp.async.commit_group;\n");
}

__global__ __launch_bounds__(TPB, 1)
void router_main(const float* __restrict__ x, const float* __restrict__ Wg,
                 const int* __restrict__ pk, float* __restrict__ out,
                 int N, int tok_per_blk) {
    extern __shared__ float smem[];
    float* sW = smem;                              // [E*DDIM]
    float* sx = smem + E * DDIM;                   // [NW][STG][32][CFLOAT]
    __shared__ float sh_psum[E];
    __shared__ unsigned sh_cnt[E];
    __shared__ float sh_ent;

    int tid = threadIdx.x;
    int wid = tid >> 5;
    int lane = tid & 31;
    int tok0 = blockIdx.x * tok_per_blk + wid * 32;
    float* wbuf = sx + wid * (STG * WBUF);

    // Start HBM traffic immediately (warp-private buffers: no barrier needed)
    warp_issue(x, wbuf, tok0, 0, lane, N);
    warp_issue(x, wbuf, tok0, 1, lane, N);

    // Stage W (32KB) into shared; single block barrier for the whole kernel
    for (int i = tid; i < (E * DDIM) / 4; i += TPB)
        ((float4*)sW)[i] = ((const float4*)Wg)[i];
    if (tid < E) { sh_psum[tid] = 0.f; sh_cnt[tid] = 0u; }
    if (tid == 0) sh_ent = 0.f;
    __syncthreads();

    int token = tok0 + lane;
    bool valid = (wid * 32 + lane < tok_per_blk) && (token < N);

    const float4* __restrict__ w4 = (const float4*)sW;
    int swz = lane & 15;

    // Each acc[e] chain remains a STRICT ascending-d scalar fmaf sequence —
    // bit-identical to the passing kernels. Only the INTERLEAVING of the 8
    // independent chains changed: FFMAs are grouped by component so each
    // chain's consecutive FFMAs sit 8 instructions apart (>= FFMA latency 4),
    // eliminating RAW stalls without touching per-chain rounding.
    float acc[E];
#pragma unroll
    for (int e = 0; e < E; ++e) acc[e] = 0.f;

    for (int c = 0; c < NCH; ++c) {
        if (c < NCH - 1) asm volatile("cp.async.wait_group 1;\n" ::: "memory");
        else             asm volatile("cp.async.wait_group 0;\n" ::: "memory");
        __syncwarp();

        const float4* xrow = (const float4*)(wbuf + (c % STG) * WBUF + lane * CFLOAT);
#pragma unroll
        for (int j = 0; j < CSLOT; ++j) {
            float4 xv = xrow[j ^ swz];
            float4 wv[E];
#pragma unroll
            for (int e = 0; e < E; ++e)
                wv[e] = w4[e * (DDIM / 4) + c * CSLOT + j];   // warp-uniform broadcast
#pragma unroll
            for (int e = 0; e < E; ++e) acc[e] = fmaf(xv.x, wv[e].x, acc[e]);
#pragma unroll
            for (int e = 0; e < E; ++e) acc[e] = fmaf(xv.y, wv[e].y, acc[e]);
#pragma unroll
            for (int e = 0; e < E; ++e) acc[e] = fmaf(xv.z, wv[e].z, acc[e]);
#pragma unroll
            for (int e = 0; e < E; ++e) acc[e] = fmaf(xv.w, wv[e].w, acc[e]);
        }
        if (c + 2 < NCH) warp_issue(x, wbuf, tok0, c + 2, lane, N);
    }

    // ---- epilogue: softmax / top-k / stats, all in registers ----
    int kk = *pk; kk = kk < 1 ? 1 : (kk > E ? E : kk);
    float* out_dw  = out;
    float* out_idx = out + (size_t)N * kk;
    float* out_lg  = out + (size_t)2 * N * kk;

    if (valid) {
        float4* lp = (float4*)(out_lg + (size_t)token * E);
        lp[0] = make_float4(acc[0], acc[1], acc[2], acc[3]);
        lp[1] = make_float4(acc[4], acc[5], acc[6], acc[7]);
    }

    float m = acc[0];
#pragma unroll
    for (int e = 1; e < E; ++e) m = fmaxf(m, acc[e]);
    float p[E], s = 0.f;
#pragma unroll
    for (int e = 0; e < E; ++e) { p[e] = __expf(acc[e] - m); s += p[e]; }
    float inv = 1.f / s;
    float logs = __logf(s);
    float ent = 0.f;
#pragma unroll
    for (int e = 0; e < E; ++e) ent -= (p[e] * inv) * (acc[e] - m - logs);

    // top-k (values descending, ties -> lower index, matching lax.top_k)
    unsigned selmask = 0;
    float tmp[E];
#pragma unroll
    for (int e = 0; e < E; ++e) tmp[e] = p[e];
#pragma unroll
    for (int r = 0; r < E; ++r) {
        if (r < kk) {
            int bi = 0; float bv = tmp[0];
#pragma unroll
            for (int e = 1; e < E; ++e) { if (tmp[e] > bv) { bv = tmp[e]; bi = e; } }
            if (valid) {
                out_dw [(size_t)token * kk + r] = bv * inv;
                out_idx[(size_t)token * kk + r] = (float)bi;
            }
            selmask |= (1u << bi);
#pragma unroll
            for (int e = 0; e < E; ++e) if (e == bi) tmp[e] = -1.f;
        }
    }

    if (!valid) { ent = 0.f; selmask = 0u; inv = 0.f; }

    // Warp reduction -> shared atomics -> one global atomic set per block
    float entw = ent;
#pragma unroll
    for (int o = 16; o > 0; o >>= 1) entw += __shfl_xor_sync(0xffffffffu, entw, o);
    float psum[E];
#pragma unroll
    for (int e = 0; e < E; ++e) {
        float v = p[e] * inv;
#pragma unroll
        for (int o = 16; o > 0; o >>= 1) v += __shfl_xor_sync(0xffffffffu, v, o);
        psum[e] = v;
    }
    bool lane0 = (lane == 0);
    if (lane0) atomicAdd(&sh_ent, entw);
#pragma unroll
    for (int e = 0; e < E; ++e) {
        unsigned b = __ballot_sync(0xffffffffu, (selmask >> e) & 1u);
        if (lane0) {
            atomicAdd(&sh_cnt[e], (unsigned)__popc(b));
            atomicAdd(&sh_psum[e], psum[e]);
        }
    }
    __syncthreads();
    if (tid < E) {
        atomicAdd(&g_cnt[tid], sh_cnt[tid]);
        atomicAdd(&g_prob_sum[tid], sh_psum[tid]);
    }
    if (tid == E) atomicAdd(&g_ent_sum, sh_ent);

    // ---- last-block-done finalize (fused; single launch) ----
    __threadfence();
    __shared__ unsigned sh_last;
    if (tid == 0) sh_last = atomicAdd(&g_done, 1u);
    __syncthreads();
    if (sh_last != gridDim.x - 1u) return;

    if (tid == 0) {
        float* base = out + (size_t)2 * N * kk + (size_t)N * E;
        long long total_cap = (long long)((double)N * (double)kk * 1.25);
        long long per_cap = total_cap / E; if (per_cap < 1) per_cap = 1;
        float invN = 1.f / (float)N;
        float lb = 0.f; int nd = 0;
        for (int e = 0; e < E; ++e) {
            float cnt = (float)g_cnt[e];
            float usage = cnt * invN;
            float avg = g_prob_sum[e] * invN;
            lb += usage * avg;
            if ((long long)g_cnt[e] > per_cap) nd++;
            base[3 + e] = usage;
        }
        base[0] = lb * (float)E;
        float entm = g_ent_sum * invN;
        float rel = logf((float)E) - entm;
        base[1] = rel > 0.f ? rel : 0.f;
        base[2] = (float)nd;

        // Reset accumulators for the next launch / graph replay.
        for (int e = 0; e < E; ++e) { g_cnt[e] = 0u; g_prob_sum[e] = 0.f; }
        g_ent_sum = 0.f;
        g_done = 0u;
    }
}

extern "C" void kernel_launch(void* const* d_in, const int* in_sizes, int n_in,
                              void* d_out, int out_size) {
    const float* x = (const float*)d_in[0];
    const float* W = (const float*)d_in[1];
    const int*  pk = (const int*)d_in[2];
    int N = in_sizes[0] / DDIM;
    float* out = (float*)d_out;

    int grid = GRID;
    int tok_per_blk = (N + grid - 1) / grid;       // 222 for N=32768
    if (tok_per_blk > TPB) {                        // safety for other shapes
        grid = (N + TPB - 1) / TPB;
        tok_per_blk = TPB;
    }
    cudaFuncSetAttribute(router_main, cudaFuncAttributeMaxDynamicSharedMemorySize, SMEM_BYTES);
    router_main<<<grid, TPB, SMEM_BYTES>>>(x, W, pk, out, N, tok_per_blk);
}